// round 5
// baseline (speedup 1.0000x reference)
#include <cuda_runtime.h>
#include <cuda_bf16.h>
#include <cstdint>

// ---------------------------------------------------------------------------
// Problem constants (B=2, S=2048, H=1024, NH=16, NKV=8, D=128)
// ---------------------------------------------------------------------------
constexpr int B_   = 2;
constexpr int S_   = 2048;
constexpr int H_   = 1024;
constexpr int NH_  = 16;
constexpr int NKV_ = 8;
constexpr int D_   = 128;
constexpr int TOK  = B_ * S_;            // 4096 tokens

// Scratch (device globals; no allocation allowed)
__device__ float g_q [TOK * NH_  * D_];
__device__ float g_k [TOK * NKV_ * D_];
__device__ float g_v [TOK * NKV_ * D_];
// bf16 hi/lo pre-split operands
__device__ __nv_bfloat16 g_hh [TOK * H_],        g_hl [TOK * H_];         // hidden
__device__ __nv_bfloat16 g_wqh[NH_  * D_ * H_],  g_wql[NH_  * D_ * H_];
__device__ __nv_bfloat16 g_wkh[NKV_ * D_ * H_],  g_wkl[NKV_ * D_ * H_];
__device__ __nv_bfloat16 g_wvh[NKV_ * D_ * H_],  g_wvl[NKV_ * D_ * H_];
__device__ __nv_bfloat16 g_woh[H_ * NH_ * D_],   g_wol[H_ * NH_ * D_];
// attention operands / output
__device__ __nv_bfloat16 g_qh[TOK * NH_  * D_],  g_ql[TOK * NH_  * D_];
__device__ __nv_bfloat16 g_kh[TOK * NKV_ * D_],  g_kl[TOK * NKV_ * D_];
__device__ __nv_bfloat16 g_vh[TOK * NKV_ * D_],  g_vl[TOK * NKV_ * D_];
__device__ __nv_bfloat16 g_aoh[TOK * NH_ * D_],  g_aol[TOK * NH_ * D_];

#define DEV_INLINE __device__ __forceinline__

// ---------------------------------------------------------------------------
// helpers
// ---------------------------------------------------------------------------
DEV_INLINE uint32_t cvt_bf16x2(float hi_elem, float lo_elem) {
    uint32_t r;
    asm("cvt.rn.bf16x2.f32 %0, %1, %2;" : "=r"(r) : "f"(hi_elem), "f"(lo_elem));
    return r;
}
// split two fp32 (f0 -> low lane, f1 -> high lane) into bf16 hi-pair + lo-pair
DEV_INLINE void split_pair(float f0, float f1, uint32_t& hiw, uint32_t& low) {
    hiw = cvt_bf16x2(f1, f0);
    float h0 = __uint_as_float(hiw << 16);
    float h1 = __uint_as_float(hiw & 0xFFFF0000u);
    low = cvt_bf16x2(f1 - h1, f0 - h0);
}
DEV_INLINE void ldsm_x4(uint32_t* r, uint32_t addr) {
    asm volatile("ldmatrix.sync.aligned.m8n8.x4.shared.b16 {%0,%1,%2,%3}, [%4];"
                 : "=r"(r[0]), "=r"(r[1]), "=r"(r[2]), "=r"(r[3]) : "r"(addr));
}
DEV_INLINE void ldsm_x4_trans(uint32_t* r, uint32_t addr) {
    asm volatile("ldmatrix.sync.aligned.m8n8.x4.trans.shared.b16 {%0,%1,%2,%3}, [%4];"
                 : "=r"(r[0]), "=r"(r[1]), "=r"(r[2]), "=r"(r[3]) : "r"(addr));
}
DEV_INLINE void mma_bf16(float* c, const uint32_t* a, const uint32_t* b) {
    asm volatile(
        "mma.sync.aligned.m16n8k16.row.col.f32.bf16.bf16.f32 "
        "{%0,%1,%2,%3}, {%4,%5,%6,%7}, {%8,%9}, {%0,%1,%2,%3};"
        : "+f"(c[0]), "+f"(c[1]), "+f"(c[2]), "+f"(c[3])
        : "r"(a[0]), "r"(a[1]), "r"(a[2]), "r"(a[3]), "r"(b[0]), "r"(b[1]));
}
DEV_INLINE uint32_t smem_u32(const void* p) {
    uint32_t a;
    asm("{ .reg .u64 t; cvta.to.shared.u64 t, %1; cvt.u32.u64 %0, t; }"
        : "=r"(a) : "l"(p));
    return a;
}
DEV_INLINE void cp16(uint32_t dst, const void* src) {
    asm volatile("cp.async.cg.shared.global [%0], [%1], 16;"
                 :: "r"(dst), "l"(src) : "memory");
}
DEV_INLINE void cp_commit() { asm volatile("cp.async.commit_group;" ::: "memory"); }
DEV_INLINE void cp_wait1()  { asm volatile("cp.async.wait_group 1;" ::: "memory"); }
DEV_INLINE void cp_wait0()  { asm volatile("cp.async.wait_group 0;" ::: "memory"); }

// ---------------------------------------------------------------------------
// elementwise fp32 -> bf16 hi/lo splitter (grid-stride, float4 granularity)
// ---------------------------------------------------------------------------
__global__ void split_kernel(const float* __restrict__ x,
                             __nv_bfloat16* __restrict__ hi,
                             __nv_bfloat16* __restrict__ lo, int n4)
{
    int i = blockIdx.x * blockDim.x + threadIdx.x;
    const int stride = gridDim.x * blockDim.x;
    for (; i < n4; i += stride) {
        const float4 v = reinterpret_cast<const float4*>(x)[i];
        uint32_t h0, l0, h1, l1;
        split_pair(v.x, v.y, h0, l0);
        split_pair(v.z, v.w, h1, l1);
        reinterpret_cast<uint2*>(hi)[i] = make_uint2(h0, h1);
        reinterpret_cast<uint2*>(lo)[i] = make_uint2(l0, l1);
    }
}

// ---------------------------------------------------------------------------
// bf16x3 tensor-core NT GEMM with PRE-SPLIT operands.
// C[m,n] = sum_k A[m,k]*B[n,k], A = Ah+Al, B = Bh+Bl (bf16, row-major, K-cols)
// CTA tile 128x128, BK=32, 256 threads (8 warps: 4m x 2n, warp tile 32x64).
// SMEM buffer: {Ahi, Alo, Bhi, Blo} each 128 rows x 64B data, 80B stride.
// cp.async double buffered. 3 products: Ah*Bh + Ah*Bl + Al*Bh.
// ---------------------------------------------------------------------------
constexpr int GMATB = 10240;           // 128 * 80
constexpr int GBUFB = 4 * GMATB;       // 40960
constexpr int GSMEM = 2 * GBUFB;       // 81920

DEV_INLINE void gemm_issue(uint32_t buf, int r, int p0,
                           const __nv_bfloat16* Ah, const __nv_bfloat16* Al,
                           const __nv_bfloat16* Bh, const __nv_bfloat16* Bl,
                           size_t aoff, size_t boff)
{
#pragma unroll
    for (int pp = 0; pp < 2; pp++) {
        const int piece = p0 + pp;
        const uint32_t dst = buf + (uint32_t)r * 80 + piece * 16;
        cp16(dst,             Ah + aoff + piece * 8);
        cp16(dst + GMATB,     Al + aoff + piece * 8);
        cp16(dst + 2 * GMATB, Bh + boff + piece * 8);
        cp16(dst + 3 * GMATB, Bl + boff + piece * 8);
    }
}

__global__ void __launch_bounds__(256, 1)
gemm_bf16_ps(const __nv_bfloat16* __restrict__ Ah, const __nv_bfloat16* __restrict__ Al,
             const __nv_bfloat16* __restrict__ Bh, const __nv_bfloat16* __restrict__ Bl,
             float* __restrict__ C, int M, int N, int K)
{
    extern __shared__ char smem[];
    const uint32_t sb = smem_u32(smem);

    const int tid  = threadIdx.x;
    const int lane = tid & 31;
    const int wid  = tid >> 5;
    const int wm   = wid & 3;
    const int wn   = wid >> 2;
    const int m0   = blockIdx.y * 128;
    const int n0   = blockIdx.x * 128;

    const int r  = tid >> 1;             // 0..127
    const int p0 = (tid & 1) * 2;        // pieces p0, p0+1 (16B each)
    const size_t abase = (size_t)(m0 + r) * K;
    const size_t bbase = (size_t)(n0 + r) * K;

    float Cacc[2][8][4];
#pragma unroll
    for (int mi = 0; mi < 2; mi++)
#pragma unroll
        for (int nf = 0; nf < 8; nf++)
#pragma unroll
            for (int e = 0; e < 4; e++) Cacc[mi][nf][e] = 0.f;

    const uint32_t lrow = (uint32_t)(lane & 15);
    const uint32_t lcol = (uint32_t)(lane >> 4) * 16;

    // prologue: chunk 0
    gemm_issue(sb, r, p0, Ah, Al, Bh, Bl, abase, bbase);
    cp_commit();

    const int NC = K / 32;
    for (int c = 0; c < NC; c++) {
        if (c + 1 < NC) {
            gemm_issue(sb + ((c + 1) & 1) * GBUFB, r, p0, Ah, Al, Bh, Bl,
                       abase + (c + 1) * 32, bbase + (c + 1) * 32);
            cp_commit();
            cp_wait1();
        } else {
            cp_wait0();
        }
        __syncthreads();

        const uint32_t bufs = sb + (c & 1) * GBUFB;
#pragma unroll
        for (int ks = 0; ks < 2; ks++) {
            uint32_t af[2][4];
            uint32_t bfr[2][8][2];
            {
                const uint32_t addr = bufs +
                    ((uint32_t)(wm * 32) + lrow + ((lane >> 4) << 4)) * 0; // (placeholder avoidance)
            }
            // A fragments: hi (sel 0) and lo (sel 1), two 16-row m-frags
            uint32_t afrag[2][2][4];
#pragma unroll
            for (int sel = 0; sel < 2; sel++) {
#pragma unroll
                for (int mi = 0; mi < 2; mi++) {
                    const uint32_t addr = bufs + (uint32_t)sel * GMATB +
                        ((uint32_t)(wm * 32 + mi * 16) + lrow) * 80 +
                        (uint32_t)ks * 32 + lcol;
                    ldsm_x4(afrag[sel][mi], addr);
                }
#pragma unroll
                for (int ng = 0; ng < 4; ng++) {
                    uint32_t t[4];
                    const uint32_t addr = bufs + 2 * GMATB + (uint32_t)sel * GMATB +
                        ((uint32_t)(wn * 64 + ng * 16) + lrow) * 80 +
                        (uint32_t)ks * 32 + lcol;
                    ldsm_x4(t, addr);
                    bfr[sel][ng * 2][0]     = t[0];
                    bfr[sel][ng * 2][1]     = t[2];
                    bfr[sel][ng * 2 + 1][0] = t[1];
                    bfr[sel][ng * 2 + 1][1] = t[3];
                }
            }
            (void)af;
#pragma unroll
            for (int mi = 0; mi < 2; mi++)
#pragma unroll
                for (int nf = 0; nf < 8; nf++)
                    mma_bf16(Cacc[mi][nf], afrag[0][mi], bfr[0][nf]);
#pragma unroll
            for (int mi = 0; mi < 2; mi++)
#pragma unroll
                for (int nf = 0; nf < 8; nf++)
                    mma_bf16(Cacc[mi][nf], afrag[0][mi], bfr[1][nf]);
#pragma unroll
            for (int mi = 0; mi < 2; mi++)
#pragma unroll
                for (int nf = 0; nf < 8; nf++)
                    mma_bf16(Cacc[mi][nf], afrag[1][mi], bfr[0][nf]);
        }
        __syncthreads();
    }

#pragma unroll
    for (int mi = 0; mi < 2; mi++) {
        const int row = m0 + wm * 32 + mi * 16 + (lane >> 2);
#pragma unroll
        for (int nf = 0; nf < 8; nf++) {
            const int col = n0 + wn * 64 + nf * 8 + (lane & 3) * 2;
            *reinterpret_cast<float2*>(C + (size_t)row * N + col) =
                make_float2(Cacc[mi][nf][0], Cacc[mi][nf][1]);
            *reinterpret_cast<float2*>(C + (size_t)(row + 8) * N + col) =
                make_float2(Cacc[mi][nf][2], Cacc[mi][nf][3]);
        }
    }
}

// ---------------------------------------------------------------------------
// Fused RMSNorm + RoPE + bf16 hi/lo split. Warp-per-row (D=128, 4 els/lane).
// rows = TOK * 32 (hh: 0-15 q, 16-23 k, 24-31 v). 256-thread blocks, 8 rows.
// ---------------------------------------------------------------------------
__global__ void __launch_bounds__(256)
rms_rope_split2(const float* __restrict__ qbuf, const float* __restrict__ kbuf,
                const float* __restrict__ vbuf,
                const float* __restrict__ cosb, const float* __restrict__ sinb,
                const float* __restrict__ qw,   const float* __restrict__ kw,
                __nv_bfloat16* __restrict__ qh, __nv_bfloat16* __restrict__ ql,
                __nv_bfloat16* __restrict__ kh, __nv_bfloat16* __restrict__ kl,
                __nv_bfloat16* __restrict__ vh, __nv_bfloat16* __restrict__ vl)
{
    const int rrow = blockIdx.x * 8 + (threadIdx.x >> 5);
    const int l    = threadIdx.x & 31;
    const int t    = rrow >> 5;
    const int hh   = rrow & 31;

    if (hh >= 24) {                      // v: split only
        const size_t base = (size_t)t * (NKV_ * D_) + (hh - 24) * D_ + l * 4;
        const float4 x = *reinterpret_cast<const float4*>(vbuf + base);
        uint32_t h0, l0, h1, l1;
        split_pair(x.x, x.y, h0, l0);
        split_pair(x.z, x.w, h1, l1);
        *reinterpret_cast<uint2*>(vh + base) = make_uint2(h0, h1);
        *reinterpret_cast<uint2*>(vl + base) = make_uint2(l0, l1);
        return;
    }

    const float* src; const float* w;
    __nv_bfloat16 *oh, *ol;
    size_t base;
    if (hh < 16) {
        base = (size_t)t * (NH_ * D_) + hh * D_ + l * 4;
        src = qbuf; w = qw; oh = qh; ol = ql;
    } else {
        base = (size_t)t * (NKV_ * D_) + (hh - 16) * D_ + l * 4;
        src = kbuf; w = kw; oh = kh; ol = kl;
    }

    const float4 x = *reinterpret_cast<const float4*>(src + base);
    float ss = x.x * x.x + x.y * x.y + x.z * x.z + x.w * x.w;
#pragma unroll
    for (int off = 16; off >= 1; off >>= 1) ss += __shfl_xor_sync(0xffffffffu, ss, off);
    const float inv = rsqrtf(ss * (1.0f / 128.0f) + 1e-6f);

    const float4 wv = *reinterpret_cast<const float4*>(w + l * 4);
    const float4 cv = *reinterpret_cast<const float4*>(cosb + (size_t)t * D_ + l * 4);
    const float4 sv = *reinterpret_cast<const float4*>(sinb + (size_t)t * D_ + l * 4);

    // weighted values; rotate-half partner lives at lane l^16, same slot
    const float z0 = x.x * wv.x, z1 = x.y * wv.y, z2 = x.z * wv.z, z3 = x.w * wv.w;
    const float p0 = __shfl_xor_sync(0xffffffffu, z0, 16);
    const float p1 = __shfl_xor_sync(0xffffffffu, z1, 16);
    const float p2 = __shfl_xor_sync(0xffffffffu, z2, 16);
    const float p3 = __shfl_xor_sync(0xffffffffu, z3, 16);
    const float sgn = (l < 16) ? -1.f : 1.f;

    const float y0 = (z0 * cv.x + sgn * p0 * sv.x) * inv;
    const float y1 = (z1 * cv.y + sgn * p1 * sv.y) * inv;
    const float y2 = (z2 * cv.z + sgn * p2 * sv.z) * inv;
    const float y3 = (z3 * cv.w + sgn * p3 * sv.w) * inv;

    uint32_t h0, l0w, h1, l1w;
    split_pair(y0, y1, h0, l0w);
    split_pair(y2, y3, h1, l1w);
    *reinterpret_cast<uint2*>(oh + base) = make_uint2(h0, h1);
    *reinterpret_cast<uint2*>(ol + base) = make_uint2(l0w, l1w);
}

// ---------------------------------------------------------------------------
// Tensor-core flash attention (bf16x3, causal, GQA n_rep=2). Output bf16 hi/lo.
// BQ=128, BKV=64, D=128. 256 threads = 8 warps, warp w -> q rows w*16..+15.
// ---------------------------------------------------------------------------
constexpr int AQ_BYTES  = 128 * 272;                 // 34816
constexpr int AKV_BYTES = 64 * 272;                  // 17408
constexpr int ABUF0     = 2 * AQ_BYTES;              // 69632
constexpr int ABUFSZ    = 4 * AKV_BYTES;             // 69632
constexpr int ATTN_SMEM = ABUF0 + 2 * ABUFSZ;        // 208896

__global__ void __launch_bounds__(256, 1)
attn_bf16_kernel(const __nv_bfloat16* __restrict__ qh, const __nv_bfloat16* __restrict__ ql,
                 const __nv_bfloat16* __restrict__ kh, const __nv_bfloat16* __restrict__ kl,
                 const __nv_bfloat16* __restrict__ vh, const __nv_bfloat16* __restrict__ vl,
                 __nv_bfloat16* __restrict__ aoh, __nv_bfloat16* __restrict__ aol)
{
    extern __shared__ char smem[];
    const uint32_t sb = smem_u32(smem);

    const int tid  = threadIdx.x;
    const int lane = tid & 31;
    const int w    = tid >> 5;
    const int qi   = gridDim.x - 1 - blockIdx.x;
    const int h    = blockIdx.y;
    const int b    = blockIdx.z;
    const int kvh  = h >> 1;

#pragma unroll
    for (int i = 0; i < 8; i++) {
        const int idx = tid + i * 256;
        const int row = idx >> 4, ch = idx & 15;
        const size_t g = ((size_t)(b * S_) + qi * 128 + row) * (NH_ * D_) + h * D_ + ch * 8;
        cp16(sb + row * 272 + ch * 16,            qh + g);
        cp16(sb + AQ_BYTES + row * 272 + ch * 16, ql + g);
    }
    {
        const uint32_t buf = sb + ABUF0;
#pragma unroll
        for (int i = 0; i < 4; i++) {
            const int idx = tid + i * 256;
            const int row = idx >> 4, ch = idx & 15;
            const size_t g = ((size_t)(b * S_) + row) * (NKV_ * D_) + kvh * D_ + ch * 8;
            const uint32_t so = buf + row * 272 + ch * 16;
            cp16(so,                 kh + g);
            cp16(so + AKV_BYTES,     kl + g);
            cp16(so + 2 * AKV_BYTES, vh + g);
            cp16(so + 3 * AKV_BYTES, vl + g);
        }
    }
    cp_commit();

    float oacc[16][4];
#pragma unroll
    for (int i = 0; i < 16; i++)
#pragma unroll
        for (int e = 0; e < 4; e++) oacc[i][e] = 0.f;
    float m_i[2] = {-1e30f, -1e30f};
    float l_i[2] = {0.f, 0.f};

    const uint32_t lrow16 = (uint32_t)(lane & 15);
    const uint32_t lhalf  = (uint32_t)(lane >> 4) * 16;
    const int jmax = 2 * qi + 1;

    for (int jb = 0; jb <= jmax; jb++) {
        if (jb < jmax) {
            const uint32_t buf = sb + ABUF0 + ((jb + 1) & 1) * ABUFSZ;
#pragma unroll
            for (int i = 0; i < 4; i++) {
                const int idx = tid + i * 256;
                const int row = idx >> 4, ch = idx & 15;
                const size_t g = ((size_t)(b * S_) + (jb + 1) * 64 + row) * (NKV_ * D_) +
                                 kvh * D_ + ch * 8;
                const uint32_t so = buf + row * 272 + ch * 16;
                cp16(so,                 kh + g);
                cp16(so + AKV_BYTES,     kl + g);
                cp16(so + 2 * AKV_BYTES, vh + g);
                cp16(so + 3 * AKV_BYTES, vl + g);
            }
            cp_commit();
            cp_wait1();
        } else {
            cp_wait0();
        }
        __syncthreads();

        const uint32_t kb = sb + ABUF0 + (jb & 1) * ABUFSZ;
        const bool skip = (jb * 64) > (qi * 128 + w * 16 + 15);

        if (!skip) {
            float sacc[8][4];
#pragma unroll
            for (int i = 0; i < 8; i++)
#pragma unroll
                for (int e = 0; e < 4; e++) sacc[i][e] = 0.f;

            const uint32_t qbase = sb + ((uint32_t)(w * 16) + lrow16) * 272 + lhalf;
#pragma unroll
            for (int ks = 0; ks < 8; ks++) {
                uint32_t ahi[4], alo[4];
                ldsm_x4(ahi, qbase + ks * 32);
                ldsm_x4(alo, qbase + AQ_BYTES + ks * 32);
#pragma unroll
                for (int ng = 0; ng < 4; ng++) {
                    uint32_t t[4], u[4];
                    const uint32_t ka = kb + ((uint32_t)(ng * 16) + lrow16) * 272 + ks * 32 + lhalf;
                    ldsm_x4(t, ka);
                    ldsm_x4(u, ka + AKV_BYTES);
                    uint32_t bh0[2] = {t[0], t[2]}, bh1[2] = {t[1], t[3]};
                    uint32_t bl0[2] = {u[0], u[2]}, bl1[2] = {u[1], u[3]};
                    mma_bf16(sacc[ng * 2],     ahi, bh0);
                    mma_bf16(sacc[ng * 2 + 1], ahi, bh1);
                    mma_bf16(sacc[ng * 2],     ahi, bl0);
                    mma_bf16(sacc[ng * 2 + 1], ahi, bl1);
                    mma_bf16(sacc[ng * 2],     alo, bh0);
                    mma_bf16(sacc[ng * 2 + 1], alo, bh1);
                }
            }

            const float sc = 0.088388347648318447f;
            const bool domask = (jb * 64 + 63) > (qi * 128 + w * 16);
#pragma unroll
            for (int nf = 0; nf < 8; nf++)
#pragma unroll
                for (int e = 0; e < 4; e++) {
                    float s = sacc[nf][e] * sc;
                    if (domask) {
                        const int col = jb * 64 + nf * 8 + ((lane & 3) << 1) + (e & 1);
                        const int row = qi * 128 + w * 16 + (lane >> 2) + ((e >> 1) << 3);
                        if (col > row) s = -1e30f;
                    }
                    sacc[nf][e] = s;
                }

#pragma unroll
            for (int r2 = 0; r2 < 2; r2++) {
                float mx = -1e30f;
#pragma unroll
                for (int nf = 0; nf < 8; nf++)
                    mx = fmaxf(mx, fmaxf(sacc[nf][2 * r2], sacc[nf][2 * r2 + 1]));
                mx = fmaxf(mx, __shfl_xor_sync(0xffffffffu, mx, 1));
                mx = fmaxf(mx, __shfl_xor_sync(0xffffffffu, mx, 2));
                const float mn = fmaxf(m_i[r2], mx);
                const float alpha = __expf(m_i[r2] - mn);
                m_i[r2] = mn;
                float rs = 0.f;
#pragma unroll
                for (int nf = 0; nf < 8; nf++) {
                    float p0 = __expf(sacc[nf][2 * r2]     - mn);
                    float p1 = __expf(sacc[nf][2 * r2 + 1] - mn);
                    sacc[nf][2 * r2]     = p0;
                    sacc[nf][2 * r2 + 1] = p1;
                    rs += p0 + p1;
                }
                rs += __shfl_xor_sync(0xffffffffu, rs, 1);
                rs += __shfl_xor_sync(0xffffffffu, rs, 2);
                l_i[r2] = l_i[r2] * alpha + rs;
#pragma unroll
                for (int ndf = 0; ndf < 16; ndf++) {
                    oacc[ndf][2 * r2]     *= alpha;
                    oacc[ndf][2 * r2 + 1] *= alpha;
                }
            }

#pragma unroll
            for (int kk = 0; kk < 4; kk++) {
                uint32_t phi[4], plo[4];
                split_pair(sacc[2 * kk][0],     sacc[2 * kk][1],     phi[0], plo[0]);
                split_pair(sacc[2 * kk][2],     sacc[2 * kk][3],     phi[1], plo[1]);
                split_pair(sacc[2 * kk + 1][0], sacc[2 * kk + 1][1], phi[2], plo[2]);
                split_pair(sacc[2 * kk + 1][2], sacc[2 * kk + 1][3], phi[3], plo[3]);
#pragma unroll
                for (int ndg = 0; ndg < 8; ndg++) {
                    uint32_t t[4], u[4];
                    const uint32_t va = kb + 2 * AKV_BYTES +
                        ((uint32_t)(kk * 16) + lrow16) * 272 + ndg * 32 + lhalf;
                    ldsm_x4_trans(t, va);
                    ldsm_x4_trans(u, va + AKV_BYTES);
                    uint32_t bh0[2] = {t[0], t[1]}, bh1[2] = {t[2], t[3]};
                    uint32_t bl0[2] = {u[0], u[1]}, bl1[2] = {u[2], u[3]};
                    mma_bf16(oacc[ndg * 2],     phi, bh0);
                    mma_bf16(oacc[ndg * 2 + 1], phi, bh1);
                    mma_bf16(oacc[ndg * 2],     phi, bl0);
                    mma_bf16(oacc[ndg * 2 + 1], phi, bl1);
                    mma_bf16(oacc[ndg * 2],     plo, bh0);
                    mma_bf16(oacc[ndg * 2 + 1], plo, bh1);
                }
            }
        }
        __syncthreads();
    }

    // epilogue: normalize, split to bf16 hi/lo, store
    const float i0 = 1.0f / l_i[0];
    const float i1 = 1.0f / l_i[1];
    const int row0 = qi * 128 + w * 16 + (lane >> 2);
    const size_t base0 = ((size_t)(b * S_) + row0) * (NH_ * D_) + h * D_ + (lane & 3) * 2;
    const size_t base1 = base0 + (size_t)8 * (NH_ * D_);
#pragma unroll
    for (int ndf = 0; ndf < 16; ndf++) {
        uint32_t hw, lw;
        split_pair(oacc[ndf][0] * i0, oacc[ndf][1] * i0, hw, lw);
        *reinterpret_cast<uint32_t*>(&aoh[base0 + ndf * 8]) = hw;
        *reinterpret_cast<uint32_t*>(&aol[base0 + ndf * 8]) = lw;
        split_pair(oacc[ndf][2] * i1, oacc[ndf][3] * i1, hw, lw);
        *reinterpret_cast<uint32_t*>(&aoh[base1 + ndf * 8]) = hw;
        *reinterpret_cast<uint32_t*>(&aol[base1 + ndf * 8]) = lw;
    }
}

// ---------------------------------------------------------------------------
// Launch
// ---------------------------------------------------------------------------
extern "C" void kernel_launch(void* const* d_in, const int* in_sizes, int n_in,
                              void* d_out, int out_size)
{
    const float* hidden = (const float*)d_in[0];
    const float* cosb   = (const float*)d_in[1];
    const float* sinb   = (const float*)d_in[2];
    const float* Wq     = (const float*)d_in[3];
    const float* Wk     = (const float*)d_in[4];
    const float* Wv     = (const float*)d_in[5];
    const float* Wo     = (const float*)d_in[6];
    const float* qw     = (const float*)d_in[7];
    const float* kw     = (const float*)d_in[8];
    float* out = (float*)d_out;

    float *gq, *gk, *gv;
    cudaGetSymbolAddress((void**)&gq, g_q);
    cudaGetSymbolAddress((void**)&gk, g_k);
    cudaGetSymbolAddress((void**)&gv, g_v);
    __nv_bfloat16 *hh, *hl, *wqh, *wql, *wkh, *wkl, *wvh, *wvl, *woh, *wol;
    cudaGetSymbolAddress((void**)&hh,  g_hh);   cudaGetSymbolAddress((void**)&hl,  g_hl);
    cudaGetSymbolAddress((void**)&wqh, g_wqh);  cudaGetSymbolAddress((void**)&wql, g_wql);
    cudaGetSymbolAddress((void**)&wkh, g_wkh);  cudaGetSymbolAddress((void**)&wkl, g_wkl);
    cudaGetSymbolAddress((void**)&wvh, g_wvh);  cudaGetSymbolAddress((void**)&wvl, g_wvl);
    cudaGetSymbolAddress((void**)&woh, g_woh);  cudaGetSymbolAddress((void**)&wol, g_wol);
    __nv_bfloat16 *qh, *ql, *kh, *kl, *vh, *vl, *aoh, *aol;
    cudaGetSymbolAddress((void**)&qh,  g_qh);   cudaGetSymbolAddress((void**)&ql,  g_ql);
    cudaGetSymbolAddress((void**)&kh,  g_kh);   cudaGetSymbolAddress((void**)&kl,  g_kl);
    cudaGetSymbolAddress((void**)&vh,  g_vh);   cudaGetSymbolAddress((void**)&vl,  g_vl);
    cudaGetSymbolAddress((void**)&aoh, g_aoh);  cudaGetSymbolAddress((void**)&aol, g_aol);

    cudaFuncSetAttribute((const void*)gemm_bf16_ps,
                         cudaFuncAttributeMaxDynamicSharedMemorySize, GSMEM);
    cudaFuncSetAttribute((const void*)attn_bf16_kernel,
                         cudaFuncAttributeMaxDynamicSharedMemorySize, ATTN_SMEM);

    // pre-split hidden + weights (fp32 -> bf16 hi/lo)
    split_kernel<<<1024, 256>>>(hidden, hh,  hl,  TOK * H_ / 4);
    split_kernel<<<1024, 256>>>(Wq,     wqh, wql, NH_ * D_ * H_ / 4);
    split_kernel<<<512,  256>>>(Wk,     wkh, wkl, NKV_ * D_ * H_ / 4);
    split_kernel<<<512,  256>>>(Wv,     wvh, wvl, NKV_ * D_ * H_ / 4);
    split_kernel<<<1024, 256>>>(Wo,     woh, wol, H_ * NH_ * D_ / 4);

    // QKV projections (pure bf16x3 tensor GEMM)
    gemm_bf16_ps<<<dim3((NH_ * D_) / 128, TOK / 128), 256, GSMEM>>>(
        hh, hl, wqh, wql, gq, TOK, NH_ * D_, H_);
    gemm_bf16_ps<<<dim3((NKV_ * D_) / 128, TOK / 128), 256, GSMEM>>>(
        hh, hl, wkh, wkl, gk, TOK, NKV_ * D_, H_);
    gemm_bf16_ps<<<dim3((NKV_ * D_) / 128, TOK / 128), 256, GSMEM>>>(
        hh, hl, wvh, wvl, gv, TOK, NKV_ * D_, H_);

    // fused RMSNorm + RoPE + split (warp per row)
    rms_rope_split2<<<TOK * 32 / 8, 256>>>(gq, gk, gv, cosb, sinb, qw, kw,
                                           qh, ql, kh, kl, vh, vl);

    // tensor-core causal flash attention (emits bf16 hi/lo)
    attn_bf16_kernel<<<dim3(S_ / 128, NH_, B_), 256, ATTN_SMEM>>>(
        qh, ql, kh, kl, vh, vl, aoh, aol);

    // output projection (A pre-split by attention epilogue)
    gemm_bf16_ps<<<dim3(H_ / 128, TOK / 128), 256, GSMEM>>>(
        aoh, aol, woh, wol, out, TOK, H_, NH_ * D_);
}

// round 6
// speedup vs baseline: 1.1888x; 1.1888x over previous
#include <cuda_runtime.h>
#include <cuda_bf16.h>
#include <cstdint>

// ---------------------------------------------------------------------------
// Problem constants (B=2, S=2048, H=1024, NH=16, NKV=8, D=128)
// ---------------------------------------------------------------------------
constexpr int B_   = 2;
constexpr int S_   = 2048;
constexpr int H_   = 1024;
constexpr int NH_  = 16;
constexpr int NKV_ = 8;
constexpr int D_   = 128;
constexpr int TOK  = B_ * S_;            // 4096 tokens

// Scratch (device globals; no allocation allowed)
__device__ float g_q [TOK * NH_  * D_];
__device__ float g_k [TOK * NKV_ * D_];
__device__ float g_v [TOK * NKV_ * D_];
__device__ float g_ao[TOK * NH_  * D_];
// bf16 hi/lo split attention operands
__device__ __nv_bfloat16 g_qh[TOK * NH_  * D_], g_ql[TOK * NH_  * D_];
__device__ __nv_bfloat16 g_kh[TOK * NKV_ * D_], g_kl[TOK * NKV_ * D_];
__device__ __nv_bfloat16 g_vh[TOK * NKV_ * D_], g_vl[TOK * NKV_ * D_];

#define DEV_INLINE __device__ __forceinline__

// ---------------------------------------------------------------------------
// helpers
// ---------------------------------------------------------------------------
DEV_INLINE uint32_t cvt_bf16x2(float hi_elem, float lo_elem) {
    uint32_t r;
    asm("cvt.rn.bf16x2.f32 %0, %1, %2;" : "=r"(r) : "f"(hi_elem), "f"(lo_elem));
    return r;
}
// split two fp32 (f0 -> low lane, f1 -> high lane) into bf16 hi-pair + lo-pair
DEV_INLINE void split_pair(float f0, float f1, uint32_t& hiw, uint32_t& low) {
    hiw = cvt_bf16x2(f1, f0);
    float h0 = __uint_as_float(hiw << 16);
    float h1 = __uint_as_float(hiw & 0xFFFF0000u);
    low = cvt_bf16x2(f1 - h1, f0 - h0);
}
DEV_INLINE void ldsm_x4(uint32_t* r, uint32_t addr) {
    asm volatile("ldmatrix.sync.aligned.m8n8.x4.shared.b16 {%0,%1,%2,%3}, [%4];"
                 : "=r"(r[0]), "=r"(r[1]), "=r"(r[2]), "=r"(r[3]) : "r"(addr));
}
DEV_INLINE void ldsm_x4_trans(uint32_t* r, uint32_t addr) {
    asm volatile("ldmatrix.sync.aligned.m8n8.x4.trans.shared.b16 {%0,%1,%2,%3}, [%4];"
                 : "=r"(r[0]), "=r"(r[1]), "=r"(r[2]), "=r"(r[3]) : "r"(addr));
}
DEV_INLINE void mma_bf16(float* c, const uint32_t* a, const uint32_t* b) {
    asm volatile(
        "mma.sync.aligned.m16n8k16.row.col.f32.bf16.bf16.f32 "
        "{%0,%1,%2,%3}, {%4,%5,%6,%7}, {%8,%9}, {%0,%1,%2,%3};"
        : "+f"(c[0]), "+f"(c[1]), "+f"(c[2]), "+f"(c[3])
        : "r"(a[0]), "r"(a[1]), "r"(a[2]), "r"(a[3]), "r"(b[0]), "r"(b[1]));
}
DEV_INLINE uint32_t smem_u32(const void* p) {
    uint32_t a;
    asm("{ .reg .u64 t; cvta.to.shared.u64 t, %1; cvt.u32.u64 %0, t; }"
        : "=r"(a) : "l"(p));
    return a;
}
DEV_INLINE void cp16(uint32_t dst, const void* src) {
    asm volatile("cp.async.cg.shared.global [%0], [%1], 16;"
                 :: "r"(dst), "l"(src) : "memory");
}
DEV_INLINE void cp_commit() { asm volatile("cp.async.commit_group;" ::: "memory"); }
DEV_INLINE void cp_wait1()  { asm volatile("cp.async.wait_group 1;" ::: "memory"); }
DEV_INLINE void cp_wait0()  { asm volatile("cp.async.wait_group 0;" ::: "memory"); }

// ---------------------------------------------------------------------------
// bf16x3 tensor-core NT GEMM body (round-4 proven design, in-loop split).
// C[m,n] = sum_k A[m,k]*B[n,k].  CTA tile 128x128, BK=32, 256 threads
// (8 warps: 4m x 2n, warp tile 32x64). 3 products: Ah*Bh + Ah*Bl + Al*Bh.
// ---------------------------------------------------------------------------
constexpr int GMATB = 10240;           // 128 * 80 bytes per split tile
constexpr int GBUFB = 4 * GMATB;       // 40960 per double-buffer slot
constexpr int GSMEM = 2 * GBUFB;       // 81920

DEV_INLINE void gemm_body(const float* __restrict__ A, const float* __restrict__ Bm,
                          float* __restrict__ C, int K, int N, int m0, int n0,
                          char* smem, uint32_t sb)
{
    const int tid  = threadIdx.x;
    const int lane = tid & 31;
    const int wid  = tid >> 5;
    const int wm   = wid & 3;
    const int wn   = wid >> 2;

    const int r    = tid >> 1;          // tile row 0..127
    const int half = tid & 1;           // 16-col half
    const float* Arow = A  + (size_t)(m0 + r) * K + half * 16;
    const float* Brow = Bm + (size_t)(n0 + r) * K + half * 16;

    float Cacc[2][8][4];
#pragma unroll
    for (int mi = 0; mi < 2; mi++)
#pragma unroll
        for (int nf = 0; nf < 8; nf++)
#pragma unroll
            for (int e = 0; e < 4; e++) Cacc[mi][nf][e] = 0.f;

    float4 ra[4], rb[4];
#pragma unroll
    for (int i = 0; i < 4; i++) {
        ra[i] = *reinterpret_cast<const float4*>(Arow + i * 4);
        rb[i] = *reinterpret_cast<const float4*>(Brow + i * 4);
    }

    const uint32_t lrow = (uint32_t)(lane & 15);
    const uint32_t lcol = (uint32_t)(lane >> 4) * 16;

    const int NC = K / 32;
    for (int c = 0; c < NC; c++) {
        char* bp = smem + (c & 1) * GBUFB;
        const uint32_t bufs = sb + (c & 1) * GBUFB;

        {   // split + store this chunk
            uint32_t hiw[8], low[8];
#pragma unroll
            for (int i = 0; i < 4; i++) {
                split_pair(ra[i].x, ra[i].y, hiw[i * 2],     low[i * 2]);
                split_pair(ra[i].z, ra[i].w, hiw[i * 2 + 1], low[i * 2 + 1]);
            }
            const uint32_t off = (uint32_t)r * 80 + (uint32_t)half * 32;
            *reinterpret_cast<uint4*>(bp + off)              = make_uint4(hiw[0], hiw[1], hiw[2], hiw[3]);
            *reinterpret_cast<uint4*>(bp + off + 16)         = make_uint4(hiw[4], hiw[5], hiw[6], hiw[7]);
            *reinterpret_cast<uint4*>(bp + GMATB + off)      = make_uint4(low[0], low[1], low[2], low[3]);
            *reinterpret_cast<uint4*>(bp + GMATB + off + 16) = make_uint4(low[4], low[5], low[6], low[7]);
#pragma unroll
            for (int i = 0; i < 4; i++) {
                split_pair(rb[i].x, rb[i].y, hiw[i * 2],     low[i * 2]);
                split_pair(rb[i].z, rb[i].w, hiw[i * 2 + 1], low[i * 2 + 1]);
            }
            *reinterpret_cast<uint4*>(bp + 2 * GMATB + off)      = make_uint4(hiw[0], hiw[1], hiw[2], hiw[3]);
            *reinterpret_cast<uint4*>(bp + 2 * GMATB + off + 16) = make_uint4(hiw[4], hiw[5], hiw[6], hiw[7]);
            *reinterpret_cast<uint4*>(bp + 3 * GMATB + off)      = make_uint4(low[0], low[1], low[2], low[3]);
            *reinterpret_cast<uint4*>(bp + 3 * GMATB + off + 16) = make_uint4(low[4], low[5], low[6], low[7]);
        }
        __syncthreads();

        if (c + 1 < NC) {               // register prefetch of next chunk
            const int k0 = (c + 1) * 32;
#pragma unroll
            for (int i = 0; i < 4; i++) {
                ra[i] = *reinterpret_cast<const float4*>(Arow + k0 + i * 4);
                rb[i] = *reinterpret_cast<const float4*>(Brow + k0 + i * 4);
            }
        }

#pragma unroll
        for (int ks = 0; ks < 2; ks++) {
            uint32_t afrag[2][2][4];
            uint32_t bfr[2][8][2];
#pragma unroll
            for (int sel = 0; sel < 2; sel++) {
#pragma unroll
                for (int mi = 0; mi < 2; mi++) {
                    const uint32_t addr = bufs + (uint32_t)sel * GMATB +
                        ((uint32_t)(wm * 32 + mi * 16) + lrow) * 80 +
                        (uint32_t)ks * 32 + lcol;
                    ldsm_x4(afrag[sel][mi], addr);
                }
#pragma unroll
                for (int ng = 0; ng < 4; ng++) {
                    uint32_t t[4];
                    const uint32_t addr = bufs + 2 * GMATB + (uint32_t)sel * GMATB +
                        ((uint32_t)(wn * 64 + ng * 16) + lrow) * 80 +
                        (uint32_t)ks * 32 + lcol;
                    ldsm_x4(t, addr);
                    bfr[sel][ng * 2][0]     = t[0];
                    bfr[sel][ng * 2][1]     = t[2];
                    bfr[sel][ng * 2 + 1][0] = t[1];
                    bfr[sel][ng * 2 + 1][1] = t[3];
                }
            }
#pragma unroll
            for (int mi = 0; mi < 2; mi++)
#pragma unroll
                for (int nf = 0; nf < 8; nf++)
                    mma_bf16(Cacc[mi][nf], afrag[0][mi], bfr[0][nf]);
#pragma unroll
            for (int mi = 0; mi < 2; mi++)
#pragma unroll
                for (int nf = 0; nf < 8; nf++)
                    mma_bf16(Cacc[mi][nf], afrag[0][mi], bfr[1][nf]);
#pragma unroll
            for (int mi = 0; mi < 2; mi++)
#pragma unroll
                for (int nf = 0; nf < 8; nf++)
                    mma_bf16(Cacc[mi][nf], afrag[1][mi], bfr[0][nf]);
        }
        __syncthreads();
    }

#pragma unroll
    for (int mi = 0; mi < 2; mi++) {
        const int row = m0 + wm * 32 + mi * 16 + (lane >> 2);
#pragma unroll
        for (int nf = 0; nf < 8; nf++) {
            const int col = n0 + wn * 64 + nf * 8 + (lane & 3) * 2;
            *reinterpret_cast<float2*>(C + (size_t)row * N + col) =
                make_float2(Cacc[mi][nf][0], Cacc[mi][nf][1]);
            *reinterpret_cast<float2*>(C + (size_t)(row + 8) * N + col) =
                make_float2(Cacc[mi][nf][2], Cacc[mi][nf][3]);
        }
    }
}

// Merged QKV projection: grid (32 n-tiles routed, 32 m-tiles)
__global__ void __launch_bounds__(256, 1)
gemm_qkv(const float* __restrict__ A,
         const float* __restrict__ Wq, const float* __restrict__ Wk,
         const float* __restrict__ Wv,
         float* __restrict__ q, float* __restrict__ k, float* __restrict__ v)
{
    extern __shared__ char smem[];
    const uint32_t sb = smem_u32(smem);
    const int bx = blockIdx.x;
    const int m0 = blockIdx.y * 128;

    const float* Bm; float* C; int N; int n0;
    if (bx < 16)      { Bm = Wq; C = q; N = NH_ * D_;  n0 = bx * 128; }
    else if (bx < 24) { Bm = Wk; C = k; N = NKV_ * D_; n0 = (bx - 16) * 128; }
    else              { Bm = Wv; C = v; N = NKV_ * D_; n0 = (bx - 24) * 128; }

    gemm_body(A, Bm, C, H_, N, m0, n0, smem, sb);
}

// Generic GEMM (output projection)
__global__ void __launch_bounds__(256, 1)
gemm_nt(const float* __restrict__ A, const float* __restrict__ Bm,
        float* __restrict__ C, int M, int N, int K)
{
    extern __shared__ char smem[];
    const uint32_t sb = smem_u32(smem);
    gemm_body(A, Bm, C, K, N, blockIdx.y * 128, blockIdx.x * 128, smem, sb);
}

// ---------------------------------------------------------------------------
// Fused RMSNorm + RoPE + bf16 hi/lo split. Warp-per-row (D=128, 4 els/lane).
// rows = TOK * 32 (hh: 0-15 q, 16-23 k, 24-31 v). 256-thread blocks, 8 rows.
// ---------------------------------------------------------------------------
__global__ void __launch_bounds__(256)
rms_rope_split2(const float* __restrict__ qbuf, const float* __restrict__ kbuf,
                const float* __restrict__ vbuf,
                const float* __restrict__ cosb, const float* __restrict__ sinb,
                const float* __restrict__ qw,   const float* __restrict__ kw,
                __nv_bfloat16* __restrict__ qh, __nv_bfloat16* __restrict__ ql,
                __nv_bfloat16* __restrict__ kh, __nv_bfloat16* __restrict__ kl,
                __nv_bfloat16* __restrict__ vh, __nv_bfloat16* __restrict__ vl)
{
    const int rrow = blockIdx.x * 8 + (threadIdx.x >> 5);
    const int l    = threadIdx.x & 31;
    const int t    = rrow >> 5;
    const int hh   = rrow & 31;

    if (hh >= 24) {                      // v: split only
        const size_t base = (size_t)t * (NKV_ * D_) + (hh - 24) * D_ + l * 4;
        const float4 x = *reinterpret_cast<const float4*>(vbuf + base);
        uint32_t h0, l0, h1, l1;
        split_pair(x.x, x.y, h0, l0);
        split_pair(x.z, x.w, h1, l1);
        *reinterpret_cast<uint2*>(vh + base) = make_uint2(h0, h1);
        *reinterpret_cast<uint2*>(vl + base) = make_uint2(l0, l1);
        return;
    }

    const float* src; const float* w;
    __nv_bfloat16 *oh, *ol;
    size_t base;
    if (hh < 16) {
        base = (size_t)t * (NH_ * D_) + hh * D_ + l * 4;
        src = qbuf; w = qw; oh = qh; ol = ql;
    } else {
        base = (size_t)t * (NKV_ * D_) + (hh - 16) * D_ + l * 4;
        src = kbuf; w = kw; oh = kh; ol = kl;
    }

    const float4 x = *reinterpret_cast<const float4*>(src + base);
    float ss = x.x * x.x + x.y * x.y + x.z * x.z + x.w * x.w;
#pragma unroll
    for (int off = 16; off >= 1; off >>= 1) ss += __shfl_xor_sync(0xffffffffu, ss, off);
    const float inv = rsqrtf(ss * (1.0f / 128.0f) + 1e-6f);

    const float4 wv = *reinterpret_cast<const float4*>(w + l * 4);
    const float4 cv = *reinterpret_cast<const float4*>(cosb + (size_t)t * D_ + l * 4);
    const float4 sv = *reinterpret_cast<const float4*>(sinb + (size_t)t * D_ + l * 4);

    const float z0 = x.x * wv.x, z1 = x.y * wv.y, z2 = x.z * wv.z, z3 = x.w * wv.w;
    const float p0 = __shfl_xor_sync(0xffffffffu, z0, 16);
    const float p1 = __shfl_xor_sync(0xffffffffu, z1, 16);
    const float p2 = __shfl_xor_sync(0xffffffffu, z2, 16);
    const float p3 = __shfl_xor_sync(0xffffffffu, z3, 16);
    const float sgn = (l < 16) ? -1.f : 1.f;

    const float y0 = (z0 * cv.x + sgn * p0 * sv.x) * inv;
    const float y1 = (z1 * cv.y + sgn * p1 * sv.y) * inv;
    const float y2 = (z2 * cv.z + sgn * p2 * sv.z) * inv;
    const float y3 = (z3 * cv.w + sgn * p3 * sv.w) * inv;

    uint32_t h0, l0w, h1, l1w;
    split_pair(y0, y1, h0, l0w);
    split_pair(y2, y3, h1, l1w);
    *reinterpret_cast<uint2*>(oh + base) = make_uint2(h0, h1);
    *reinterpret_cast<uint2*>(ol + base) = make_uint2(l0w, l1w);
}

// ---------------------------------------------------------------------------
// Tensor-core flash attention (bf16x3, causal, GQA n_rep=2). Round-4 proven.
// BQ=128, BKV=64, D=128. 256 threads = 8 warps, warp w -> q rows w*16..+15.
// ---------------------------------------------------------------------------
constexpr int AQ_BYTES  = 128 * 272;                 // 34816
constexpr int AKV_BYTES = 64 * 272;                  // 17408
constexpr int ABUF0     = 2 * AQ_BYTES;              // 69632
constexpr int ABUFSZ    = 4 * AKV_BYTES;             // 69632
constexpr int ATTN_SMEM = ABUF0 + 2 * ABUFSZ;        // 208896

__global__ void __launch_bounds__(256, 1)
attn_bf16_kernel(const __nv_bfloat16* __restrict__ qh, const __nv_bfloat16* __restrict__ ql,
                 const __nv_bfloat16* __restrict__ kh, const __nv_bfloat16* __restrict__ kl,
                 const __nv_bfloat16* __restrict__ vh, const __nv_bfloat16* __restrict__ vl,
                 float* __restrict__ ao)
{
    extern __shared__ char smem[];
    const uint32_t sb = smem_u32(smem);

    const int tid  = threadIdx.x;
    const int lane = tid & 31;
    const int w    = tid >> 5;
    const int qi   = gridDim.x - 1 - blockIdx.x;
    const int h    = blockIdx.y;
    const int b    = blockIdx.z;
    const int kvh  = h >> 1;

#pragma unroll
    for (int i = 0; i < 8; i++) {
        const int idx = tid + i * 256;
        const int row = idx >> 4, ch = idx & 15;
        const size_t g = ((size_t)(b * S_) + qi * 128 + row) * (NH_ * D_) + h * D_ + ch * 8;
        cp16(sb + row * 272 + ch * 16,            qh + g);
        cp16(sb + AQ_BYTES + row * 272 + ch * 16, ql + g);
    }
    {
        const uint32_t buf = sb + ABUF0;
#pragma unroll
        for (int i = 0; i < 4; i++) {
            const int idx = tid + i * 256;
            const int row = idx >> 4, ch = idx & 15;
            const size_t g = ((size_t)(b * S_) + row) * (NKV_ * D_) + kvh * D_ + ch * 8;
            const uint32_t so = buf + row * 272 + ch * 16;
            cp16(so,                 kh + g);
            cp16(so + AKV_BYTES,     kl + g);
            cp16(so + 2 * AKV_BYTES, vh + g);
            cp16(so + 3 * AKV_BYTES, vl + g);
        }
    }
    cp_commit();

    float oacc[16][4];
#pragma unroll
    for (int i = 0; i < 16; i++)
#pragma unroll
        for (int e = 0; e < 4; e++) oacc[i][e] = 0.f;
    float m_i[2] = {-1e30f, -1e30f};
    float l_i[2] = {0.f, 0.f};

    const uint32_t lrow16 = (uint32_t)(lane & 15);
    const uint32_t lhalf  = (uint32_t)(lane >> 4) * 16;
    const int jmax = 2 * qi + 1;

    for (int jb = 0; jb <= jmax; jb++) {
        if (jb < jmax) {
            const uint32_t buf = sb + ABUF0 + ((jb + 1) & 1) * ABUFSZ;
#pragma unroll
            for (int i = 0; i < 4; i++) {
                const int idx = tid + i * 256;
                const int row = idx >> 4, ch = idx & 15;
                const size_t g = ((size_t)(b * S_) + (jb + 1) * 64 + row) * (NKV_ * D_) +
                                 kvh * D_ + ch * 8;
                const uint32_t so = buf + row * 272 + ch * 16;
                cp16(so,                 kh + g);
                cp16(so + AKV_BYTES,     kl + g);
                cp16(so + 2 * AKV_BYTES, vh + g);
                cp16(so + 3 * AKV_BYTES, vl + g);
            }
            cp_commit();
            cp_wait1();
        } else {
            cp_wait0();
        }
        __syncthreads();

        const uint32_t kb = sb + ABUF0 + (jb & 1) * ABUFSZ;
        const bool skip = (jb * 64) > (qi * 128 + w * 16 + 15);

        if (!skip) {
            float sacc[8][4];
#pragma unroll
            for (int i = 0; i < 8; i++)
#pragma unroll
                for (int e = 0; e < 4; e++) sacc[i][e] = 0.f;

            const uint32_t qbase = sb + ((uint32_t)(w * 16) + lrow16) * 272 + lhalf;
#pragma unroll
            for (int ks = 0; ks < 8; ks++) {
                uint32_t ahi[4], alo[4];
                ldsm_x4(ahi, qbase + ks * 32);
                ldsm_x4(alo, qbase + AQ_BYTES + ks * 32);
#pragma unroll
                for (int ng = 0; ng < 4; ng++) {
                    uint32_t t[4], u[4];
                    const uint32_t ka = kb + ((uint32_t)(ng * 16) + lrow16) * 272 + ks * 32 + lhalf;
                    ldsm_x4(t, ka);
                    ldsm_x4(u, ka + AKV_BYTES);
                    uint32_t bh0[2] = {t[0], t[2]}, bh1[2] = {t[1], t[3]};
                    uint32_t bl0[2] = {u[0], u[2]}, bl1[2] = {u[1], u[3]};
                    mma_bf16(sacc[ng * 2],     ahi, bh0);
                    mma_bf16(sacc[ng * 2 + 1], ahi, bh1);
                    mma_bf16(sacc[ng * 2],     ahi, bl0);
                    mma_bf16(sacc[ng * 2 + 1], ahi, bl1);
                    mma_bf16(sacc[ng * 2],     alo, bh0);
                    mma_bf16(sacc[ng * 2 + 1], alo, bh1);
                }
            }

            const float sc = 0.088388347648318447f;
            const bool domask = (jb * 64 + 63) > (qi * 128 + w * 16);
#pragma unroll
            for (int nf = 0; nf < 8; nf++)
#pragma unroll
                for (int e = 0; e < 4; e++) {
                    float s = sacc[nf][e] * sc;
                    if (domask) {
                        const int col = jb * 64 + nf * 8 + ((lane & 3) << 1) + (e & 1);
                        const int row = qi * 128 + w * 16 + (lane >> 2) + ((e >> 1) << 3);
                        if (col > row) s = -1e30f;
                    }
                    sacc[nf][e] = s;
                }

#pragma unroll
            for (int r2 = 0; r2 < 2; r2++) {
                float mx = -1e30f;
#pragma unroll
                for (int nf = 0; nf < 8; nf++)
                    mx = fmaxf(mx, fmaxf(sacc[nf][2 * r2], sacc[nf][2 * r2 + 1]));
                mx = fmaxf(mx, __shfl_xor_sync(0xffffffffu, mx, 1));
                mx = fmaxf(mx, __shfl_xor_sync(0xffffffffu, mx, 2));
                const float mn = fmaxf(m_i[r2], mx);
                const float alpha = __expf(m_i[r2] - mn);
                m_i[r2] = mn;
                float rs = 0.f;
#pragma unroll
                for (int nf = 0; nf < 8; nf++) {
                    float p0 = __expf(sacc[nf][2 * r2]     - mn);
                    float p1 = __expf(sacc[nf][2 * r2 + 1] - mn);
                    sacc[nf][2 * r2]     = p0;
                    sacc[nf][2 * r2 + 1] = p1;
                    rs += p0 + p1;
                }
                rs += __shfl_xor_sync(0xffffffffu, rs, 1);
                rs += __shfl_xor_sync(0xffffffffu, rs, 2);
                l_i[r2] = l_i[r2] * alpha + rs;
#pragma unroll
                for (int ndf = 0; ndf < 16; ndf++) {
                    oacc[ndf][2 * r2]     *= alpha;
                    oacc[ndf][2 * r2 + 1] *= alpha;
                }
            }

#pragma unroll
            for (int kk = 0; kk < 4; kk++) {
                uint32_t phi[4], plo[4];
                split_pair(sacc[2 * kk][0],     sacc[2 * kk][1],     phi[0], plo[0]);
                split_pair(sacc[2 * kk][2],     sacc[2 * kk][3],     phi[1], plo[1]);
                split_pair(sacc[2 * kk + 1][0], sacc[2 * kk + 1][1], phi[2], plo[2]);
                split_pair(sacc[2 * kk + 1][2], sacc[2 * kk + 1][3], phi[3], plo[3]);
#pragma unroll
                for (int ndg = 0; ndg < 8; ndg++) {
                    uint32_t t[4], u[4];
                    const uint32_t va = kb + 2 * AKV_BYTES +
                        ((uint32_t)(kk * 16) + lrow16) * 272 + ndg * 32 + lhalf;
                    ldsm_x4_trans(t, va);
                    ldsm_x4_trans(u, va + AKV_BYTES);
                    uint32_t bh0[2] = {t[0], t[1]}, bh1[2] = {t[2], t[3]};
                    uint32_t bl0[2] = {u[0], u[1]}, bl1[2] = {u[2], u[3]};
                    mma_bf16(oacc[ndg * 2],     phi, bh0);
                    mma_bf16(oacc[ndg * 2 + 1], phi, bh1);
                    mma_bf16(oacc[ndg * 2],     phi, bl0);
                    mma_bf16(oacc[ndg * 2 + 1], phi, bl1);
                    mma_bf16(oacc[ndg * 2],     plo, bh0);
                    mma_bf16(oacc[ndg * 2 + 1], plo, bh1);
                }
            }
        }
        __syncthreads();
    }

    const float i0 = 1.0f / l_i[0];
    const float i1 = 1.0f / l_i[1];
    const int row0 = qi * 128 + w * 16 + (lane >> 2);
    const size_t base0 = ((size_t)(b * S_) + row0) * (NH_ * D_) + h * D_ + (lane & 3) * 2;
    const size_t base1 = base0 + (size_t)8 * (NH_ * D_);
#pragma unroll
    for (int ndf = 0; ndf < 16; ndf++) {
        *reinterpret_cast<float2*>(ao + base0 + ndf * 8) =
            make_float2(oacc[ndf][0] * i0, oacc[ndf][1] * i0);
        *reinterpret_cast<float2*>(ao + base1 + ndf * 8) =
            make_float2(oacc[ndf][2] * i1, oacc[ndf][3] * i1);
    }
}

// ---------------------------------------------------------------------------
// Launch
// ---------------------------------------------------------------------------
extern "C" void kernel_launch(void* const* d_in, const int* in_sizes, int n_in,
                              void* d_out, int out_size)
{
    const float* hidden = (const float*)d_in[0];
    const float* cosb   = (const float*)d_in[1];
    const float* sinb   = (const float*)d_in[2];
    const float* Wq     = (const float*)d_in[3];
    const float* Wk     = (const float*)d_in[4];
    const float* Wv     = (const float*)d_in[5];
    const float* Wo     = (const float*)d_in[6];
    const float* qw     = (const float*)d_in[7];
    const float* kw     = (const float*)d_in[8];
    float* out = (float*)d_out;

    float *gq, *gk, *gv, *gao;
    cudaGetSymbolAddress((void**)&gq,  g_q);
    cudaGetSymbolAddress((void**)&gk,  g_k);
    cudaGetSymbolAddress((void**)&gv,  g_v);
    cudaGetSymbolAddress((void**)&gao, g_ao);
    __nv_bfloat16 *qh, *ql, *kh, *kl, *vh, *vl;
    cudaGetSymbolAddress((void**)&qh, g_qh);
    cudaGetSymbolAddress((void**)&ql, g_ql);
    cudaGetSymbolAddress((void**)&kh, g_kh);
    cudaGetSymbolAddress((void**)&kl, g_kl);
    cudaGetSymbolAddress((void**)&vh, g_vh);
    cudaGetSymbolAddress((void**)&vl, g_vl);

    cudaFuncSetAttribute((const void*)gemm_qkv,
                         cudaFuncAttributeMaxDynamicSharedMemorySize, GSMEM);
    cudaFuncSetAttribute((const void*)gemm_nt,
                         cudaFuncAttributeMaxDynamicSharedMemorySize, GSMEM);
    cudaFuncSetAttribute((const void*)attn_bf16_kernel,
                         cudaFuncAttributeMaxDynamicSharedMemorySize, ATTN_SMEM);

    // merged QKV projection (1024 CTAs, bf16x3 tensor GEMM)
    gemm_qkv<<<dim3(32, TOK / 128), 256, GSMEM>>>(hidden, Wq, Wk, Wv, gq, gk, gv);

    // fused RMSNorm + RoPE + split (warp per row)
    rms_rope_split2<<<TOK * 32 / 8, 256>>>(gq, gk, gv, cosb, sinb, qw, kw,
                                           qh, ql, kh, kl, vh, vl);

    // tensor-core causal flash attention
    attn_bf16_kernel<<<dim3(S_ / 128, NH_, B_), 256, ATTN_SMEM>>>(
        qh, ql, kh, kl, vh, vl, gao);

    // output projection
    gemm_nt<<<dim3(H_ / 128, TOK / 128), 256, GSMEM>>>(
        gao, Wo, out, TOK, H_, NH_ * D_);
}

// round 7
// speedup vs baseline: 1.1995x; 1.0090x over previous
#include <cuda_runtime.h>
#include <cuda_bf16.h>
#include <cstdint>

// ---------------------------------------------------------------------------
// Problem constants (B=2, S=2048, H=1024, NH=16, NKV=8, D=128)
// ---------------------------------------------------------------------------
constexpr int B_   = 2;
constexpr int S_   = 2048;
constexpr int H_   = 1024;
constexpr int NH_  = 16;
constexpr int NKV_ = 8;
constexpr int D_   = 128;
constexpr int TOK  = B_ * S_;            // 4096 tokens

// Scratch (device globals; no allocation allowed)
__device__ float g_q [TOK * NH_  * D_];
__device__ float g_k [TOK * NKV_ * D_];
__device__ float g_v [TOK * NKV_ * D_];
__device__ float g_ao[TOK * NH_  * D_];
// bf16 hi/lo split attention operands
__device__ __nv_bfloat16 g_qh[TOK * NH_  * D_], g_ql[TOK * NH_  * D_];
__device__ __nv_bfloat16 g_kh[TOK * NKV_ * D_], g_kl[TOK * NKV_ * D_];
__device__ __nv_bfloat16 g_vh[TOK * NKV_ * D_], g_vl[TOK * NKV_ * D_];

#define DEV_INLINE __device__ __forceinline__

// ---------------------------------------------------------------------------
// helpers
// ---------------------------------------------------------------------------
DEV_INLINE uint32_t cvt_bf16x2(float hi_elem, float lo_elem) {
    uint32_t r;
    asm("cvt.rn.bf16x2.f32 %0, %1, %2;" : "=r"(r) : "f"(hi_elem), "f"(lo_elem));
    return r;
}
// split two fp32 (f0 -> low lane, f1 -> high lane) into bf16 hi-pair + lo-pair
DEV_INLINE void split_pair(float f0, float f1, uint32_t& hiw, uint32_t& low) {
    hiw = cvt_bf16x2(f1, f0);
    float h0 = __uint_as_float(hiw << 16);
    float h1 = __uint_as_float(hiw & 0xFFFF0000u);
    low = cvt_bf16x2(f1 - h1, f0 - h0);
}
DEV_INLINE void ldsm_x4(uint32_t* r, uint32_t addr) {
    asm volatile("ldmatrix.sync.aligned.m8n8.x4.shared.b16 {%0,%1,%2,%3}, [%4];"
                 : "=r"(r[0]), "=r"(r[1]), "=r"(r[2]), "=r"(r[3]) : "r"(addr));
}
DEV_INLINE void ldsm_x4_trans(uint32_t* r, uint32_t addr) {
    asm volatile("ldmatrix.sync.aligned.m8n8.x4.trans.shared.b16 {%0,%1,%2,%3}, [%4];"
                 : "=r"(r[0]), "=r"(r[1]), "=r"(r[2]), "=r"(r[3]) : "r"(addr));
}
DEV_INLINE void mma_bf16(float* c, const uint32_t* a, const uint32_t* b) {
    asm volatile(
        "mma.sync.aligned.m16n8k16.row.col.f32.bf16.bf16.f32 "
        "{%0,%1,%2,%3}, {%4,%5,%6,%7}, {%8,%9}, {%0,%1,%2,%3};"
        : "+f"(c[0]), "+f"(c[1]), "+f"(c[2]), "+f"(c[3])
        : "r"(a[0]), "r"(a[1]), "r"(a[2]), "r"(a[3]), "r"(b[0]), "r"(b[1]));
}
DEV_INLINE uint32_t smem_u32(const void* p) {
    uint32_t a;
    asm("{ .reg .u64 t; cvta.to.shared.u64 t, %1; cvt.u32.u64 %0, t; }"
        : "=r"(a) : "l"(p));
    return a;
}
DEV_INLINE void cp16(uint32_t dst, const void* src) {
    asm volatile("cp.async.cg.shared.global [%0], [%1], 16;"
                 :: "r"(dst), "l"(src) : "memory");
}
DEV_INLINE void cp_commit() { asm volatile("cp.async.commit_group;" ::: "memory"); }
DEV_INLINE void cp_wait1()  { asm volatile("cp.async.wait_group 1;" ::: "memory"); }
DEV_INLINE void cp_wait0()  { asm volatile("cp.async.wait_group 0;" ::: "memory"); }

// ---------------------------------------------------------------------------
// bf16x3 tensor-core NT GEMM body — 512 threads / 16 warps (4m x 4n),
// warp tile 32x32, CTA tile 128x128, BK=32, in-loop split, double buffered.
// 3 products: Ah*Bh + Ah*Bl + Al*Bh.
// ---------------------------------------------------------------------------
constexpr int GMATB = 10240;           // 128 * 80 bytes per split tile
constexpr int GBUFB = 4 * GMATB;       // 40960 per double-buffer slot
constexpr int GSMEM = 2 * GBUFB;       // 81920

DEV_INLINE void gemm_body(const float* __restrict__ A, const float* __restrict__ Bm,
                          float* __restrict__ C, int K, int N, int m0, int n0,
                          char* smem, uint32_t sb)
{
    const int tid  = threadIdx.x;
    const int lane = tid & 31;
    const int wid  = tid >> 5;          // 0..15
    const int wm   = wid & 3;           // 4 m-warps
    const int wn   = wid >> 2;          // 4 n-warps

    // global load mapping: row r, 8-col quarter q
    const int r = tid >> 2;             // 0..127
    const int q = tid & 3;              // quarter (8 f32)
    const float* Arow = A  + (size_t)(m0 + r) * K + q * 8;
    const float* Brow = Bm + (size_t)(n0 + r) * K + q * 8;

    float Cacc[2][4][4];
#pragma unroll
    for (int mi = 0; mi < 2; mi++)
#pragma unroll
        for (int nf = 0; nf < 4; nf++)
#pragma unroll
            for (int e = 0; e < 4; e++) Cacc[mi][nf][e] = 0.f;

    float4 ra[2], rb[2];
#pragma unroll
    for (int i = 0; i < 2; i++) {
        ra[i] = *reinterpret_cast<const float4*>(Arow + i * 4);
        rb[i] = *reinterpret_cast<const float4*>(Brow + i * 4);
    }

    const uint32_t lrow = (uint32_t)(lane & 15);
    const uint32_t lcol = (uint32_t)(lane >> 4) * 16;

    const int NC = K / 32;
    for (int c = 0; c < NC; c++) {
        char* bp = smem + (c & 1) * GBUFB;
        const uint32_t bufs = sb + (c & 1) * GBUFB;

        {   // split + store this chunk (A then B); 8 f32 -> one uint4 hi + lo
            const uint32_t off = (uint32_t)r * 80 + (uint32_t)q * 16;
            uint32_t h0, l0, h1, l1, h2, l2, h3, l3;
            split_pair(ra[0].x, ra[0].y, h0, l0);
            split_pair(ra[0].z, ra[0].w, h1, l1);
            split_pair(ra[1].x, ra[1].y, h2, l2);
            split_pair(ra[1].z, ra[1].w, h3, l3);
            *reinterpret_cast<uint4*>(bp + off)         = make_uint4(h0, h1, h2, h3);
            *reinterpret_cast<uint4*>(bp + GMATB + off) = make_uint4(l0, l1, l2, l3);
            split_pair(rb[0].x, rb[0].y, h0, l0);
            split_pair(rb[0].z, rb[0].w, h1, l1);
            split_pair(rb[1].x, rb[1].y, h2, l2);
            split_pair(rb[1].z, rb[1].w, h3, l3);
            *reinterpret_cast<uint4*>(bp + 2 * GMATB + off) = make_uint4(h0, h1, h2, h3);
            *reinterpret_cast<uint4*>(bp + 3 * GMATB + off) = make_uint4(l0, l1, l2, l3);
        }
        __syncthreads();

        if (c + 1 < NC) {               // register prefetch of next chunk
            const int k0 = (c + 1) * 32;
#pragma unroll
            for (int i = 0; i < 2; i++) {
                ra[i] = *reinterpret_cast<const float4*>(Arow + k0 + i * 4);
                rb[i] = *reinterpret_cast<const float4*>(Brow + k0 + i * 4);
            }
        }

#pragma unroll
        for (int ks = 0; ks < 2; ks++) {
            uint32_t afrag[2][2][4];    // [sel][mi][4]
            uint32_t bfr[2][4][2];      // [sel][nf][2]
#pragma unroll
            for (int sel = 0; sel < 2; sel++) {
#pragma unroll
                for (int mi = 0; mi < 2; mi++) {
                    const uint32_t addr = bufs + (uint32_t)sel * GMATB +
                        ((uint32_t)(wm * 32 + mi * 16) + lrow) * 80 +
                        (uint32_t)ks * 32 + lcol;
                    ldsm_x4(afrag[sel][mi], addr);
                }
#pragma unroll
                for (int ng = 0; ng < 2; ng++) {
                    uint32_t t[4];
                    const uint32_t addr = bufs + 2 * GMATB + (uint32_t)sel * GMATB +
                        ((uint32_t)(wn * 32 + ng * 16) + lrow) * 80 +
                        (uint32_t)ks * 32 + lcol;
                    ldsm_x4(t, addr);
                    bfr[sel][ng * 2][0]     = t[0];
                    bfr[sel][ng * 2][1]     = t[2];
                    bfr[sel][ng * 2 + 1][0] = t[1];
                    bfr[sel][ng * 2 + 1][1] = t[3];
                }
            }
#pragma unroll
            for (int mi = 0; mi < 2; mi++)
#pragma unroll
                for (int nf = 0; nf < 4; nf++)
                    mma_bf16(Cacc[mi][nf], afrag[0][mi], bfr[0][nf]);
#pragma unroll
            for (int mi = 0; mi < 2; mi++)
#pragma unroll
                for (int nf = 0; nf < 4; nf++)
                    mma_bf16(Cacc[mi][nf], afrag[0][mi], bfr[1][nf]);
#pragma unroll
            for (int mi = 0; mi < 2; mi++)
#pragma unroll
                for (int nf = 0; nf < 4; nf++)
                    mma_bf16(Cacc[mi][nf], afrag[1][mi], bfr[0][nf]);
        }
        __syncthreads();
    }

#pragma unroll
    for (int mi = 0; mi < 2; mi++) {
        const int row = m0 + wm * 32 + mi * 16 + (lane >> 2);
#pragma unroll
        for (int nf = 0; nf < 4; nf++) {
            const int col = n0 + wn * 32 + nf * 8 + (lane & 3) * 2;
            *reinterpret_cast<float2*>(C + (size_t)row * N + col) =
                make_float2(Cacc[mi][nf][0], Cacc[mi][nf][1]);
            *reinterpret_cast<float2*>(C + (size_t)(row + 8) * N + col) =
                make_float2(Cacc[mi][nf][2], Cacc[mi][nf][3]);
        }
    }
}

// Merged QKV projection: grid (32 n-tiles routed, 32 m-tiles)
__global__ void __launch_bounds__(512, 1)
gemm_qkv(const float* __restrict__ A,
         const float* __restrict__ Wq, const float* __restrict__ Wk,
         const float* __restrict__ Wv,
         float* __restrict__ q, float* __restrict__ k, float* __restrict__ v)
{
    extern __shared__ char smem[];
    const uint32_t sb = smem_u32(smem);
    const int bx = blockIdx.x;
    const int m0 = blockIdx.y * 128;

    const float* Bm; float* C; int N; int n0;
    if (bx < 16)      { Bm = Wq; C = q; N = NH_ * D_;  n0 = bx * 128; }
    else if (bx < 24) { Bm = Wk; C = k; N = NKV_ * D_; n0 = (bx - 16) * 128; }
    else              { Bm = Wv; C = v; N = NKV_ * D_; n0 = (bx - 24) * 128; }

    gemm_body(A, Bm, C, H_, N, m0, n0, smem, sb);
}

// Generic GEMM (output projection)
__global__ void __launch_bounds__(512, 1)
gemm_nt(const float* __restrict__ A, const float* __restrict__ Bm,
        float* __restrict__ C, int M, int N, int K)
{
    extern __shared__ char smem[];
    const uint32_t sb = smem_u32(smem);
    gemm_body(A, Bm, C, K, N, blockIdx.y * 128, blockIdx.x * 128, smem, sb);
}

// ---------------------------------------------------------------------------
// Fused RMSNorm + RoPE + bf16 hi/lo split. Warp-per-row (D=128, 4 els/lane).
// rows = TOK * 32 (hh: 0-15 q, 16-23 k, 24-31 v). 256-thread blocks, 8 rows.
// ---------------------------------------------------------------------------
__global__ void __launch_bounds__(256)
rms_rope_split2(const float* __restrict__ qbuf, const float* __restrict__ kbuf,
                const float* __restrict__ vbuf,
                const float* __restrict__ cosb, const float* __restrict__ sinb,
                const float* __restrict__ qw,   const float* __restrict__ kw,
                __nv_bfloat16* __restrict__ qh, __nv_bfloat16* __restrict__ ql,
                __nv_bfloat16* __restrict__ kh, __nv_bfloat16* __restrict__ kl,
                __nv_bfloat16* __restrict__ vh, __nv_bfloat16* __restrict__ vl)
{
    const int rrow = blockIdx.x * 8 + (threadIdx.x >> 5);
    const int l    = threadIdx.x & 31;
    const int t    = rrow >> 5;
    const int hh   = rrow & 31;

    if (hh >= 24) {                      // v: split only
        const size_t base = (size_t)t * (NKV_ * D_) + (hh - 24) * D_ + l * 4;
        const float4 x = *reinterpret_cast<const float4*>(vbuf + base);
        uint32_t h0, l0, h1, l1;
        split_pair(x.x, x.y, h0, l0);
        split_pair(x.z, x.w, h1, l1);
        *reinterpret_cast<uint2*>(vh + base) = make_uint2(h0, h1);
        *reinterpret_cast<uint2*>(vl + base) = make_uint2(l0, l1);
        return;
    }

    const float* src; const float* w;
    __nv_bfloat16 *oh, *ol;
    size_t base;
    if (hh < 16) {
        base = (size_t)t * (NH_ * D_) + hh * D_ + l * 4;
        src = qbuf; w = qw; oh = qh; ol = ql;
    } else {
        base = (size_t)t * (NKV_ * D_) + (hh - 16) * D_ + l * 4;
        src = kbuf; w = kw; oh = kh; ol = kl;
    }

    const float4 x = *reinterpret_cast<const float4*>(src + base);
    float ss = x.x * x.x + x.y * x.y + x.z * x.z + x.w * x.w;
#pragma unroll
    for (int off = 16; off >= 1; off >>= 1) ss += __shfl_xor_sync(0xffffffffu, ss, off);
    const float inv = rsqrtf(ss * (1.0f / 128.0f) + 1e-6f);

    const float4 wv = *reinterpret_cast<const float4*>(w + l * 4);
    const float4 cv = *reinterpret_cast<const float4*>(cosb + (size_t)t * D_ + l * 4);
    const float4 sv = *reinterpret_cast<const float4*>(sinb + (size_t)t * D_ + l * 4);

    const float z0 = x.x * wv.x, z1 = x.y * wv.y, z2 = x.z * wv.z, z3 = x.w * wv.w;
    const float p0 = __shfl_xor_sync(0xffffffffu, z0, 16);
    const float p1 = __shfl_xor_sync(0xffffffffu, z1, 16);
    const float p2 = __shfl_xor_sync(0xffffffffu, z2, 16);
    const float p3 = __shfl_xor_sync(0xffffffffu, z3, 16);
    const float sgn = (l < 16) ? -1.f : 1.f;

    const float y0 = (z0 * cv.x + sgn * p0 * sv.x) * inv;
    const float y1 = (z1 * cv.y + sgn * p1 * sv.y) * inv;
    const float y2 = (z2 * cv.z + sgn * p2 * sv.z) * inv;
    const float y3 = (z3 * cv.w + sgn * p3 * sv.w) * inv;

    uint32_t h0, l0w, h1, l1w;
    split_pair(y0, y1, h0, l0w);
    split_pair(y2, y3, h1, l1w);
    *reinterpret_cast<uint2*>(oh + base) = make_uint2(h0, h1);
    *reinterpret_cast<uint2*>(ol + base) = make_uint2(l0w, l1w);
}

// ---------------------------------------------------------------------------
// Tensor-core flash attention (bf16x3, causal, GQA n_rep=2). Round-4 proven.
// BQ=128, BKV=64, D=128. 256 threads = 8 warps, warp w -> q rows w*16..+15.
// ---------------------------------------------------------------------------
constexpr int AQ_BYTES  = 128 * 272;                 // 34816
constexpr int AKV_BYTES = 64 * 272;                  // 17408
constexpr int ABUF0     = 2 * AQ_BYTES;              // 69632
constexpr int ABUFSZ    = 4 * AKV_BYTES;             // 69632
constexpr int ATTN_SMEM = ABUF0 + 2 * ABUFSZ;        // 208896

__global__ void __launch_bounds__(256, 1)
attn_bf16_kernel(const __nv_bfloat16* __restrict__ qh, const __nv_bfloat16* __restrict__ ql,
                 const __nv_bfloat16* __restrict__ kh, const __nv_bfloat16* __restrict__ kl,
                 const __nv_bfloat16* __restrict__ vh, const __nv_bfloat16* __restrict__ vl,
                 float* __restrict__ ao)
{
    extern __shared__ char smem[];
    const uint32_t sb = smem_u32(smem);

    const int tid  = threadIdx.x;
    const int lane = tid & 31;
    const int w    = tid >> 5;
    const int qi   = gridDim.x - 1 - blockIdx.x;
    const int h    = blockIdx.y;
    const int b    = blockIdx.z;
    const int kvh  = h >> 1;

#pragma unroll
    for (int i = 0; i < 8; i++) {
        const int idx = tid + i * 256;
        const int row = idx >> 4, ch = idx & 15;
        const size_t g = ((size_t)(b * S_) + qi * 128 + row) * (NH_ * D_) + h * D_ + ch * 8;
        cp16(sb + row * 272 + ch * 16,            qh + g);
        cp16(sb + AQ_BYTES + row * 272 + ch * 16, ql + g);
    }
    {
        const uint32_t buf = sb + ABUF0;
#pragma unroll
        for (int i = 0; i < 4; i++) {
            const int idx = tid + i * 256;
            const int row = idx >> 4, ch = idx & 15;
            const size_t g = ((size_t)(b * S_) + row) * (NKV_ * D_) + kvh * D_ + ch * 8;
            const uint32_t so = buf + row * 272 + ch * 16;
            cp16(so,                 kh + g);
            cp16(so + AKV_BYTES,     kl + g);
            cp16(so + 2 * AKV_BYTES, vh + g);
            cp16(so + 3 * AKV_BYTES, vl + g);
        }
    }
    cp_commit();

    float oacc[16][4];
#pragma unroll
    for (int i = 0; i < 16; i++)
#pragma unroll
        for (int e = 0; e < 4; e++) oacc[i][e] = 0.f;
    float m_i[2] = {-1e30f, -1e30f};
    float l_i[2] = {0.f, 0.f};

    const uint32_t lrow16 = (uint32_t)(lane & 15);
    const uint32_t lhalf  = (uint32_t)(lane >> 4) * 16;
    const int jmax = 2 * qi + 1;

    for (int jb = 0; jb <= jmax; jb++) {
        if (jb < jmax) {
            const uint32_t buf = sb + ABUF0 + ((jb + 1) & 1) * ABUFSZ;
#pragma unroll
            for (int i = 0; i < 4; i++) {
                const int idx = tid + i * 256;
                const int row = idx >> 4, ch = idx & 15;
                const size_t g = ((size_t)(b * S_) + (jb + 1) * 64 + row) * (NKV_ * D_) +
                                 kvh * D_ + ch * 8;
                const uint32_t so = buf + row * 272 + ch * 16;
                cp16(so,                 kh + g);
                cp16(so + AKV_BYTES,     kl + g);
                cp16(so + 2 * AKV_BYTES, vh + g);
                cp16(so + 3 * AKV_BYTES, vl + g);
            }
            cp_commit();
            cp_wait1();
        } else {
            cp_wait0();
        }
        __syncthreads();

        const uint32_t kb = sb + ABUF0 + (jb & 1) * ABUFSZ;
        const bool skip = (jb * 64) > (qi * 128 + w * 16 + 15);

        if (!skip) {
            float sacc[8][4];
#pragma unroll
            for (int i = 0; i < 8; i++)
#pragma unroll
                for (int e = 0; e < 4; e++) sacc[i][e] = 0.f;

            const uint32_t qbase = sb + ((uint32_t)(w * 16) + lrow16) * 272 + lhalf;
#pragma unroll
            for (int ks = 0; ks < 8; ks++) {
                uint32_t ahi[4], alo[4];
                ldsm_x4(ahi, qbase + ks * 32);
                ldsm_x4(alo, qbase + AQ_BYTES + ks * 32);
#pragma unroll
                for (int ng = 0; ng < 4; ng++) {
                    uint32_t t[4], u[4];
                    const uint32_t ka = kb + ((uint32_t)(ng * 16) + lrow16) * 272 + ks * 32 + lhalf;
                    ldsm_x4(t, ka);
                    ldsm_x4(u, ka + AKV_BYTES);
                    uint32_t bh0[2] = {t[0], t[2]}, bh1[2] = {t[1], t[3]};
                    uint32_t bl0[2] = {u[0], u[2]}, bl1[2] = {u[1], u[3]};
                    mma_bf16(sacc[ng * 2],     ahi, bh0);
                    mma_bf16(sacc[ng * 2 + 1], ahi, bh1);
                    mma_bf16(sacc[ng * 2],     ahi, bl0);
                    mma_bf16(sacc[ng * 2 + 1], ahi, bl1);
                    mma_bf16(sacc[ng * 2],     alo, bh0);
                    mma_bf16(sacc[ng * 2 + 1], alo, bh1);
                }
            }

            const float sc = 0.088388347648318447f;
            const bool domask = (jb * 64 + 63) > (qi * 128 + w * 16);
#pragma unroll
            for (int nf = 0; nf < 8; nf++)
#pragma unroll
                for (int e = 0; e < 4; e++) {
                    float s = sacc[nf][e] * sc;
                    if (domask) {
                        const int col = jb * 64 + nf * 8 + ((lane & 3) << 1) + (e & 1);
                        const int row = qi * 128 + w * 16 + (lane >> 2) + ((e >> 1) << 3);
                        if (col > row) s = -1e30f;
                    }
                    sacc[nf][e] = s;
                }

#pragma unroll
            for (int r2 = 0; r2 < 2; r2++) {
                float mx = -1e30f;
#pragma unroll
                for (int nf = 0; nf < 8; nf++)
                    mx = fmaxf(mx, fmaxf(sacc[nf][2 * r2], sacc[nf][2 * r2 + 1]));
                mx = fmaxf(mx, __shfl_xor_sync(0xffffffffu, mx, 1));
                mx = fmaxf(mx, __shfl_xor_sync(0xffffffffu, mx, 2));
                const float mn = fmaxf(m_i[r2], mx);
                const float alpha = __expf(m_i[r2] - mn);
                m_i[r2] = mn;
                float rs = 0.f;
#pragma unroll
                for (int nf = 0; nf < 8; nf++) {
                    float p0 = __expf(sacc[nf][2 * r2]     - mn);
                    float p1 = __expf(sacc[nf][2 * r2 + 1] - mn);
                    sacc[nf][2 * r2]     = p0;
                    sacc[nf][2 * r2 + 1] = p1;
                    rs += p0 + p1;
                }
                rs += __shfl_xor_sync(0xffffffffu, rs, 1);
                rs += __shfl_xor_sync(0xffffffffu, rs, 2);
                l_i[r2] = l_i[r2] * alpha + rs;
#pragma unroll
                for (int ndf = 0; ndf < 16; ndf++) {
                    oacc[ndf][2 * r2]     *= alpha;
                    oacc[ndf][2 * r2 + 1] *= alpha;
                }
            }

#pragma unroll
            for (int kk = 0; kk < 4; kk++) {
                uint32_t phi[4], plo[4];
                split_pair(sacc[2 * kk][0],     sacc[2 * kk][1],     phi[0], plo[0]);
                split_pair(sacc[2 * kk][2],     sacc[2 * kk][3],     phi[1], plo[1]);
                split_pair(sacc[2 * kk + 1][0], sacc[2 * kk + 1][1], phi[2], plo[2]);
                split_pair(sacc[2 * kk + 1][2], sacc[2 * kk + 1][3], phi[3], plo[3]);
#pragma unroll
                for (int ndg = 0; ndg < 8; ndg++) {
                    uint32_t t[4], u[4];
                    const uint32_t va = kb + 2 * AKV_BYTES +
                        ((uint32_t)(kk * 16) + lrow16) * 272 + ndg * 32 + lhalf;
                    ldsm_x4_trans(t, va);
                    ldsm_x4_trans(u, va + AKV_BYTES);
                    uint32_t bh0[2] = {t[0], t[1]}, bh1[2] = {t[2], t[3]};
                    uint32_t bl0[2] = {u[0], u[1]}, bl1[2] = {u[2], u[3]};
                    mma_bf16(oacc[ndg * 2],     phi, bh0);
                    mma_bf16(oacc[ndg * 2 + 1], phi, bh1);
                    mma_bf16(oacc[ndg * 2],     phi, bl0);
                    mma_bf16(oacc[ndg * 2 + 1], phi, bl1);
                    mma_bf16(oacc[ndg * 2],     plo, bh0);
                    mma_bf16(oacc[ndg * 2 + 1], plo, bh1);
                }
            }
        }
        __syncthreads();
    }

    const float i0 = 1.0f / l_i[0];
    const float i1 = 1.0f / l_i[1];
    const int row0 = qi * 128 + w * 16 + (lane >> 2);
    const size_t base0 = ((size_t)(b * S_) + row0) * (NH_ * D_) + h * D_ + (lane & 3) * 2;
    const size_t base1 = base0 + (size_t)8 * (NH_ * D_);
#pragma unroll
    for (int ndf = 0; ndf < 16; ndf++) {
        *reinterpret_cast<float2*>(ao + base0 + ndf * 8) =
            make_float2(oacc[ndf][0] * i0, oacc[ndf][1] * i0);
        *reinterpret_cast<float2*>(ao + base1 + ndf * 8) =
            make_float2(oacc[ndf][2] * i1, oacc[ndf][3] * i1);
    }
}

// ---------------------------------------------------------------------------
// Launch
// ---------------------------------------------------------------------------
extern "C" void kernel_launch(void* const* d_in, const int* in_sizes, int n_in,
                              void* d_out, int out_size)
{
    const float* hidden = (const float*)d_in[0];
    const float* cosb   = (const float*)d_in[1];
    const float* sinb   = (const float*)d_in[2];
    const float* Wq     = (const float*)d_in[3];
    const float* Wk     = (const float*)d_in[4];
    const float* Wv     = (const float*)d_in[5];
    const float* Wo     = (const float*)d_in[6];
    const float* qw     = (const float*)d_in[7];
    const float* kw     = (const float*)d_in[8];
    float* out = (float*)d_out;

    float *gq, *gk, *gv, *gao;
    cudaGetSymbolAddress((void**)&gq,  g_q);
    cudaGetSymbolAddress((void**)&gk,  g_k);
    cudaGetSymbolAddress((void**)&gv,  g_v);
    cudaGetSymbolAddress((void**)&gao, g_ao);
    __nv_bfloat16 *qh, *ql, *kh, *kl, *vh, *vl;
    cudaGetSymbolAddress((void**)&qh, g_qh);
    cudaGetSymbolAddress((void**)&ql, g_ql);
    cudaGetSymbolAddress((void**)&kh, g_kh);
    cudaGetSymbolAddress((void**)&kl, g_kl);
    cudaGetSymbolAddress((void**)&vh, g_vh);
    cudaGetSymbolAddress((void**)&vl, g_vl);

    cudaFuncSetAttribute((const void*)gemm_qkv,
                         cudaFuncAttributeMaxDynamicSharedMemorySize, GSMEM);
    cudaFuncSetAttribute((const void*)gemm_nt,
                         cudaFuncAttributeMaxDynamicSharedMemorySize, GSMEM);
    cudaFuncSetAttribute((const void*)attn_bf16_kernel,
                         cudaFuncAttributeMaxDynamicSharedMemorySize, ATTN_SMEM);

    // merged QKV projection (1024 CTAs, 512 threads, bf16x3 tensor GEMM)
    gemm_qkv<<<dim3(32, TOK / 128), 512, GSMEM>>>(hidden, Wq, Wk, Wv, gq, gk, gv);

    // fused RMSNorm + RoPE + split (warp per row)
    rms_rope_split2<<<TOK * 32 / 8, 256>>>(gq, gk, gv, cosb, sinb, qw, kw,
                                           qh, ql, kh, kl, vh, vl);

    // tensor-core causal flash attention
    attn_bf16_kernel<<<dim3(S_ / 128, NH_, B_), 256, ATTN_SMEM>>>(
        qh, ql, kh, kl, vh, vl, gao);

    // output projection
    gemm_nt<<<dim3(H_ / 128, TOK / 128), 512, GSMEM>>>(
        gao, Wo, out, TOK, H_, NH_ * D_);
}